// round 9
// baseline (speedup 1.0000x reference)
#include <cuda_runtime.h>
#include <math.h>

#define T_MAX 2000
#define B_N   64
#define A_N   32
#define L_N   200
#define S_N   401          // 2*L+1

#define NTHREADS 128
#define NWARPS   4
#define PF       8         // rows per LDG burst; PF/2 fused iterations per group

__device__ float    d_per_batch[B_N];
__device__ unsigned g_ticket = 0;

__device__ __forceinline__ float ex2(float x) {
    float r; asm("ex2.approx.ftz.f32 %0, %1;" : "=f"(r) : "f"(x)); return r;
}
__device__ __forceinline__ float lg2(float x) {
    float r; asm("lg2.approx.ftz.f32 %0, %1;" : "=f"(r) : "f"(x)); return r;
}
__device__ __forceinline__ float lse2_2(float x, float y) {
    float h = fmaxf(x, y), l = fminf(x, y);
    return h + lg2(1.0f + ex2(l - h));
}
__device__ __forceinline__ float lse2_3(float x, float y, float z) {
    float h = fmaxf(x, y), l = fminf(x, y);
    float m = fmaxf(h, z), s = fminf(h, z);
    return m + lg2(1.0f + ex2(s - m) + ex2(l - m));
}

__global__ __launch_bounds__(NTHREADS, 1)
void ctc_alpha_kernel(const float* __restrict__ pred,      // (T,B,A) log-softmax (ln)
                      const int*   __restrict__ target,    // (B,L)
                      const int*   __restrict__ pred_lens,
                      const int*   __restrict__ target_lens,
                      float*       __restrict__ out)
{
    const int b    = blockIdx.x;
    const int tid  = threadIdx.x;
    const int wid  = tid >> 5;
    const int lane = tid & 31;

    __shared__ float rows[2][PF * A_N];    // double-buffered e-rows, log2 domain
    __shared__ float bnd[2][NWARPS][4];    // {b1,b0,a1,-} per warp, double-buffered
    __shared__ float fin[2];

    const float LOG2E   = 1.4426950408889634f;
    const float LN2     = 0.6931471805599453f;
    const float NEG_BIG = -1e30f;
    const float L2_EPS  = -13.287712379549449f;  // log2(0.0001)
    const float L2_HALF = -1.0028901240599430f;  // log2(0.499)

    const int Tb   = pred_lens[b];
    const int TbM1 = Tb - 1;
    const int tl   = target_lens[b];

    // Final-state owners: f0 = alpha[2tl-1] (odd), f1 = alpha[2tl] (even)
    const int  s0 = 2 * tl - 1, s1 = 2 * tl;
    const bool f0_here = (tid == (s0 >> 2));
    const bool f0_isB  = ((s0 >> 1) & 1) != 0;
    const bool f1_here = (tid == (s1 >> 2));
    const bool f1_isB  = ((s1 >> 1) & 1) != 0;

    // Own symbols (states 4t+1 -> target[2t], 4t+3 -> target[2t+1])
    int symA = 0, symB = 0;
    if (tid < L_N / 2) {
        int2 sv = ((const int2*)(target + b * L_N))[tid];
        symA = sv.x; symB = sv.y;
    }
    // Halo symbol: state 4t-1 -> target[2t-1]
    int symBL = 0;
    {
        int li = 2 * tid - 1;
        if (li >= 0 && li < L_N) symBL = target[b * L_N + li];
    }

    const size_t stride_t = (size_t)B_N * A_N;
    const float* __restrict__ pred_b = pred + (size_t)b * A_N;

    // Register alphas (log2): pair A = (4t,4t+1), pair B = (4t+2,4t+3)
    float a0 = (tid == 0) ? L2_HALF : L2_EPS;
    float a1 = (tid == 0) ? L2_HALF : L2_EPS;
    float b0 = L2_EPS;
    float b1 = L2_EPS;
    float f0c = L2_EPS, f1c = L2_EPS;

    // First fused iteration reads bnd[0]: t=0 boundary values of warp w-1
    if (tid < NWARPS) {
        bnd[0][tid][0] = L2_EPS;  // b1 (state 128w-1)
        bnd[0][tid][1] = L2_EPS;  // b0
        bnd[0][tid][2] = L2_EPS;  // a1
    }

    const int roff0 = tid >> 5;        // 0..3
    const int roff1 = roff0 + 4;       // 4..7
    rows[0][tid]       = pred_b[(size_t)min(1 + roff0, T_MAX - 1) * stride_t + lane] * LOG2E;
    rows[0][tid + 128] = pred_b[(size_t)min(1 + roff1, T_MAX - 1) * stride_t + lane] * LOG2E;
    float pf0 = pred_b[(size_t)min(9 + roff0, T_MAX - 1) * stride_t + lane];
    float pf1 = pred_b[(size_t)min(9 + roff1, T_MAX - 1) * stride_t + lane];
    __syncthreads();

    int phase = 0;
    for (int base = 1; base < Tb; base += PF) {
        #pragma unroll
        for (int u = 0; u < PF / 2; ++u) {      // each u = 2 time steps
            const int t  = base + 2 * u;
            const int rb = u & 1;
            const float* __restrict__ rc1 = &rows[phase][(2 * u)     * A_N];
            const float* __restrict__ rc2 = &rows[phase][(2 * u + 1) * A_N];

            const float eb1  = rc1[0];
            const float esA1 = rc1[symA];
            const float esB1 = rc1[symB];
            const float esBL = rc1[symBL];
            const float eb2  = rc2[0];
            const float esA2 = rc2[symA];
            const float esB2 = rc2[symB];

            // Left-neighbor values at time t-1: states 4i-1, 4i-2, 4i-3
            float bL1 = __shfl_up_sync(0xffffffffu, b1, 1);
            float bL0 = __shfl_up_sync(0xffffffffu, b0, 1);
            float aL1 = __shfl_up_sync(0xffffffffu, a1, 1);
            if (lane == 0) {
                if (wid == 0) { bL1 = NEG_BIG; bL0 = NEG_BIG; aL1 = NEG_BIG; }
                else {
                    bL1 = bnd[rb][wid - 1][0];
                    bL0 = bnd[rb][wid - 1][1];
                    aL1 = bnd[rb][wid - 1][2];
                }
            }

            // ---- step t (all 5 lse's mutually independent) ----
            float na0 = eb1  + lse2_2(a0, bL1);
            float na1 = esA1 + lse2_3(a0, bL1, a1);
            float nb0 = eb1  + lse2_2(b0, a1);
            float nb1 = esB1 + lse2_3(b0, a1, b1);
            float hb1 = esBL + lse2_3(bL1, bL0, aL1);   // halo: alpha_t[4i-1]

            if (t == TbM1) {
                if (f0_here) f0c = f0_isB ? nb1 : na1;
                if (f1_here) f1c = f1_isB ? nb0 : na0;
            }

            // ---- step t+1 (uses step-t results + halo; all local) ----
            a0 = eb2  + lse2_2(na0, hb1);
            a1 = esA2 + lse2_3(na0, hb1, na1);
            b0 = eb2  + lse2_2(nb0, na1);
            b1 = esB2 + lse2_3(nb0, na1, nb1);

            if (t + 1 == TbM1) {
                if (f0_here) f0c = f0_isB ? b1 : a1;
                if (f1_here) f1c = f1_isB ? b0 : a0;
            }

            if (lane == 31) {
                bnd[rb ^ 1][wid][0] = b1;
                bnd[rb ^ 1][wid][1] = b0;
                bnd[rb ^ 1][wid][2] = a1;
            }

            if (u == PF / 2 - 1) {
                rows[phase ^ 1][tid]       = pf0 * LOG2E;
                rows[phase ^ 1][tid + 128] = pf1 * LOG2E;
                pf0 = pred_b[(size_t)min(t + 2 + PF + roff0, T_MAX - 1) * stride_t + lane];
                pf1 = pred_b[(size_t)min(t + 2 + PF + roff1, T_MAX - 1) * stride_t + lane];
                phase ^= 1;
            }
            __syncthreads();
        }
    }

    if (f0_here) fin[0] = f0c;
    if (f1_here) fin[1] = f1c;
    __syncthreads();

    if (tid == 0) {
        d_per_batch[b] = LN2 * lse2_2(fin[0], fin[1]);
        __threadfence();
        unsigned old = atomicAdd(&g_ticket, 1u);
        if (old == B_N - 1) {
            float s = 0.0f;
            #pragma unroll 4
            for (int i = 0; i < B_N; ++i)
                s += __ldcg(&d_per_batch[i]);   // fixed order -> deterministic
            out[0] = -s * (1.0f / (float)B_N);
            g_ticket = 0;                       // reset for next graph replay
        }
    }
}

extern "C" void kernel_launch(void* const* d_in, const int* in_sizes, int n_in,
                              void* d_out, int out_size)
{
    const float* prediction  = (const float*)d_in[0];
    const int*   target      = (const int*)  d_in[1];
    const int*   pred_lens   = (const int*)  d_in[2];
    const int*   target_lens = (const int*)  d_in[3];

    ctc_alpha_kernel<<<B_N, NTHREADS>>>(prediction, target, pred_lens, target_lens,
                                        (float*)d_out);
}